// round 2
// baseline (speedup 1.0000x reference)
#include <cuda_runtime.h>
#include <cstdint>
#include <math.h>

#define BSZ 64
#define TSZ 512
#define ESZ 256
#define USZ 512
#define GSZ 2048
#define NBLK 128
#define RTHREADS 128

// Scratch (static device allocations only — no cudaMalloc allowed)
__device__ float g_xz[(size_t)2 * TSZ * USZ * 4 * BSZ];   // [dir][t][u][gate][b]  512MB
__device__ float g_h[2][2][USZ * BSZ];                    // [dir][parity][u][b]
__device__ unsigned g_bar_cnt;
__device__ unsigned g_pad_[31];                           // keep cnt/gen on separate lines
__device__ unsigned g_bar_gen;

__device__ __forceinline__ void grid_barrier() {
    __syncthreads();
    if (threadIdx.x == 0) {
        __threadfence();
        unsigned gen = atomicAdd(&g_bar_gen, 0u);
        unsigned a = atomicAdd(&g_bar_cnt, 1u);
        if (a == NBLK - 1) {
            atomicExch(&g_bar_cnt, 0u);
            __threadfence();
            atomicAdd(&g_bar_gen, 1u);
        } else {
            while (atomicAdd(&g_bar_gen, 0u) == gen) { __nanosleep(32); }
        }
        __threadfence();
    }
    __syncthreads();
}

// ---------------------------------------------------------------------------
// Kernel 1: xz[dir][t][u][g][b] = (emb[idx[b][t]] @ W_dir + b_dir), gather fused
// ---------------------------------------------------------------------------
__global__ void __launch_bounds__(256) xz_gemm_kernel(
    const int* __restrict__ idx, const float* __restrict__ emb,
    const float* __restrict__ Wf, const float* __restrict__ bf,
    const float* __restrict__ Wb, const float* __restrict__ bb)
{
    const int dir = blockIdx.z;
    const float* __restrict__ W    = dir ? Wb : Wf;
    const float* __restrict__ bias = dir ? bb : bf;
    float* __restrict__ xz = g_xz + (size_t)dir * TSZ * USZ * 4 * BSZ;

    __shared__ float As[16 * 128];
    __shared__ float Bs[16 * 64];
    __shared__ int rowv[128];

    const int tid   = threadIdx.x;
    const int rbase = blockIdx.y * 128;   // rows r = t*64 + b
    const int nbase = blockIdx.x * 64;

    if (tid < 128) {
        int r = rbase + tid;
        int t = r >> 6, b = r & 63;
        rowv[tid] = idx[b * TSZ + t];
    }
    __syncthreads();

    const int ty = tid >> 4, tx = tid & 15;
    float acc[8][4];
#pragma unroll
    for (int i = 0; i < 8; i++)
#pragma unroll
        for (int j = 0; j < 4; j++) acc[i][j] = 0.f;

    const int lm  = tid >> 1;
    const int lkq = (tid & 1) * 8;
    const int lrow = rowv[lm];
    const int lk  = tid >> 4;
    const int ln4 = (tid & 15) * 4;

    for (int kt = 0; kt < ESZ; kt += 16) {
        float4 a0 = *(const float4*)&emb[(size_t)lrow * ESZ + kt + lkq];
        float4 a1 = *(const float4*)&emb[(size_t)lrow * ESZ + kt + lkq + 4];
        float4 bv = *(const float4*)&W[(size_t)(kt + lk) * GSZ + nbase + ln4];

        As[(lkq + 0) * 128 + lm] = a0.x;
        As[(lkq + 1) * 128 + lm] = a0.y;
        As[(lkq + 2) * 128 + lm] = a0.z;
        As[(lkq + 3) * 128 + lm] = a0.w;
        As[(lkq + 4) * 128 + lm] = a1.x;
        As[(lkq + 5) * 128 + lm] = a1.y;
        As[(lkq + 6) * 128 + lm] = a1.z;
        As[(lkq + 7) * 128 + lm] = a1.w;
        *(float4*)&Bs[lk * 64 + ln4] = bv;
        __syncthreads();

#pragma unroll
        for (int k = 0; k < 16; ++k) {
            float4 rb = *(const float4*)&Bs[k * 64 + tx * 4];
#pragma unroll
            for (int i = 0; i < 8; ++i) {
                float ra = As[k * 128 + ty * 8 + i];
                acc[i][0] += ra * rb.x;
                acc[i][1] += ra * rb.y;
                acc[i][2] += ra * rb.z;
                acc[i][3] += ra * rb.w;
            }
        }
        __syncthreads();
    }

    // epilogue: rows r0..r0+7 share one t (8 | 64), store [t][u][g][b] layout
    const int r0 = rbase + ty * 8;
    const int t  = r0 >> 6;
    const int b0 = r0 & 63;
#pragma unroll
    for (int j = 0; j < 4; ++j) {
        int n = nbase + tx * 4 + j;
        int u = n & 511, g = n >> 9;
        float bv = bias[n];
        float* p = &xz[(((size_t)t * USZ + u) * 4 + g) * BSZ + b0];
        float4 v0 = { acc[0][j] + bv, acc[1][j] + bv, acc[2][j] + bv, acc[3][j] + bv };
        float4 v1 = { acc[4][j] + bv, acc[5][j] + bv, acc[6][j] + bv, acc[7][j] + bv };
        *(float4*)p       = v0;
        *(float4*)(p + 4) = v1;
    }
}

// ---------------------------------------------------------------------------
// Kernel 2: persistent bidirectional LSTM scan.
// 128 blocks: dir = bid>>6, units [ublock*8, ublock*8+8).
// U slice cached in smem for all 512 steps; h double-buffered in global,
// staged to smem per step; c/h state in registers; 1 grid barrier / step.
// ---------------------------------------------------------------------------
__global__ void __launch_bounds__(RTHREADS) lstm_scan_kernel(
    const int* __restrict__ idx,
    const float* __restrict__ Uf, const float* __restrict__ Ub,
    float* __restrict__ out)
{
    extern __shared__ float smem[];
    float* Us = smem;                         // [k][32]  (ul*4+g), 64KB
    float* hs = smem + 16384;                 // [k][64], 128KB
    unsigned long long* msk = (unsigned long long*)(smem + 16384 + 32768); // 512 x u64

    const int tid    = threadIdx.x;
    const int bid    = blockIdx.x;
    const int dir    = bid >> 6;
    const int ublock = bid & 63;
    const int bg     = tid & 15;
    const int ul     = tid >> 4;
    const int u      = ublock * 8 + ul;
    const float* __restrict__ Um = dir ? Ub : Uf;
    const float* __restrict__ xz = g_xz + (size_t)dir * TSZ * USZ * 4 * BSZ;

    // one-time: stage this block's U slice (gate-interleaved) into smem
    for (int i = tid; i < 16384; i += RTHREADS) {
        int k = i >> 5;
        int r = i & 31;
        int uu = ublock * 8 + (r >> 2);
        int g  = r & 3;
        Us[i] = Um[(size_t)k * GSZ + g * USZ + uu];
    }
    // one-time: build mask bitfields
    for (int tt = tid * 4; tt < tid * 4 + 4; ++tt) {
        unsigned long long m = 0ull;
        for (int b = 0; b < 64; ++b)
            if (idx[b * TSZ + tt] != 0) m |= (1ull << b);
        msk[tt] = m;
    }
    // init h parity-0 buffer to zero for own units
    {
        float4 z4 = { 0.f, 0.f, 0.f, 0.f };
        *(float4*)&g_h[dir][0][u * BSZ + bg * 4] = z4;
    }
    grid_barrier();

    float c_st[4] = { 0.f, 0.f, 0.f, 0.f };
    float h_st[4] = { 0.f, 0.f, 0.f, 0.f };

    for (int s = 0; s < TSZ; ++s) {
        const int t   = dir ? (TSZ - 1 - s) : s;
        const int cur = s & 1, nxt = cur ^ 1;

        // stage full h [512][64] into smem
        {
            const float4* src = (const float4*)&g_h[dir][cur][0];
            float4* dst = (float4*)hs;
#pragma unroll
            for (int i = 0; i < 64; ++i)
                dst[tid + i * RTHREADS] = src[tid + i * RTHREADS];
        }
        __syncthreads();

        float acc[4][4];
        const float* xzt = xz + (((size_t)t * USZ + u) * 4) * BSZ;
#pragma unroll
        for (int g = 0; g < 4; ++g) {
            float4 v = *(const float4*)&xzt[g * BSZ + bg * 4];
            acc[0][g] = v.x; acc[1][g] = v.y; acc[2][g] = v.z; acc[3][g] = v.w;
        }

        const float4* hs4 = (const float4*)hs;
        const float4* us4 = (const float4*)Us;
#pragma unroll 4
        for (int k = 0; k < USZ; ++k) {
            float4 hv = hs4[k * 16 + bg];   // 4 batches
            float4 uv = us4[k * 8 + ul];    // 4 gates
            acc[0][0] += hv.x * uv.x; acc[0][1] += hv.x * uv.y;
            acc[0][2] += hv.x * uv.z; acc[0][3] += hv.x * uv.w;
            acc[1][0] += hv.y * uv.x; acc[1][1] += hv.y * uv.y;
            acc[1][2] += hv.y * uv.z; acc[1][3] += hv.y * uv.w;
            acc[2][0] += hv.z * uv.x; acc[2][1] += hv.z * uv.y;
            acc[2][2] += hv.z * uv.z; acc[2][3] += hv.z * uv.w;
            acc[3][0] += hv.w * uv.x; acc[3][1] += hv.w * uv.y;
            acc[3][2] += hv.w * uv.z; acc[3][3] += hv.w * uv.w;
        }

        const unsigned long long mw = msk[t];
#pragma unroll
        for (int bi = 0; bi < 4; ++bi) {
            int b = bg * 4 + bi;
            float zi = acc[bi][0], zf = acc[bi][1], zg = acc[bi][2], zo = acc[bi][3];
            float ig = 1.f / (1.f + expf(-zi));
            float fg = 1.f / (1.f + expf(-zf));
            float gg = tanhf(zg);
            float og = 1.f / (1.f + expf(-zo));
            float cn = fg * c_st[bi] + ig * gg;
            float hn = og * tanhf(cn);
            if ((mw >> b) & 1ull) { c_st[bi] = cn; h_st[bi] = hn; }
            out[((size_t)b * TSZ + t) * 1024 + dir * USZ + u] = h_st[bi];
        }
        {
            float4 hv = { h_st[0], h_st[1], h_st[2], h_st[3] };
            *(float4*)&g_h[dir][nxt][u * BSZ + bg * 4] = hv;
        }
        grid_barrier();
    }

    // final states
    const size_t H0 = (size_t)BSZ * TSZ * 1024;
    const size_t C0 = H0 + (size_t)BSZ * 1024;
#pragma unroll
    for (int bi = 0; bi < 4; ++bi) {
        int b = bg * 4 + bi;
        out[H0 + (size_t)b * 1024 + dir * USZ + u] = h_st[bi];
        out[C0 + (size_t)b * 1024 + dir * USZ + u] = c_st[bi];
    }
}

// ---------------------------------------------------------------------------
extern "C" void kernel_launch(void* const* d_in, const int* in_sizes, int n_in,
                              void* d_out, int out_size)
{
    const int*   idx = (const int*)  d_in[0];
    const float* emb = (const float*)d_in[1];
    const float* Wf  = (const float*)d_in[2];
    const float* Uf  = (const float*)d_in[3];
    const float* bf  = (const float*)d_in[4];
    const float* Wb  = (const float*)d_in[5];
    const float* Ub  = (const float*)d_in[6];
    const float* bb  = (const float*)d_in[7];
    float* out = (float*)d_out;

    // xz GEMM: grid (N/64, M/128, dirs)
    dim3 ggrid(GSZ / 64, (BSZ * TSZ) / 128, 2);
    xz_gemm_kernel<<<ggrid, 256>>>(idx, emb, Wf, bf, Wb, bb);

    // persistent scan
    const int smem_bytes = (16384 + 32768) * 4 + 512 * 8;  // 200704
    cudaFuncSetAttribute(lstm_scan_kernel,
                         cudaFuncAttributeMaxDynamicSharedMemorySize, smem_bytes);
    lstm_scan_kernel<<<NBLK, RTHREADS, smem_bytes>>>(idx, Uf, Ub, out);
}